// round 8
// baseline (speedup 1.0000x reference)
#include <cuda_runtime.h>
#include <cuda_bf16.h>
#include <cstdint>

#define NEG_INF_F (-1.0e12f)

constexpr int S_  = 1024;
constexpr int D_  = 128;
constexpr int BH_ = 32;   // B*H

static __device__ float g_scores[(size_t)BH_ * S_ * S_];
static __device__ float g_thresh[(size_t)BH_ * S_];   // rowmax + 2*tau

// ---------------------------------------------------------------------------
// PTX helpers
// ---------------------------------------------------------------------------
__device__ __forceinline__ void ldsm4(uint32_t* r, uint32_t addr) {
    asm volatile("ldmatrix.sync.aligned.m8n8.x4.shared.b16 {%0,%1,%2,%3}, [%4];\n"
                 : "=r"(r[0]), "=r"(r[1]), "=r"(r[2]), "=r"(r[3]) : "r"(addr));
}
__device__ __forceinline__ void ldsm4t(uint32_t* r, uint32_t addr) {
    asm volatile("ldmatrix.sync.aligned.m8n8.x4.trans.shared.b16 {%0,%1,%2,%3}, [%4];\n"
                 : "=r"(r[0]), "=r"(r[1]), "=r"(r[2]), "=r"(r[3]) : "r"(addr));
}
__device__ __forceinline__ void mma_bf16(float* c, const uint32_t* a,
                                         uint32_t b0, uint32_t b1) {
    asm volatile("mma.sync.aligned.m16n8k16.row.col.f32.bf16.bf16.f32 "
                 "{%0,%1,%2,%3}, {%4,%5,%6,%7}, {%8,%9}, {%0,%1,%2,%3};\n"
                 : "+f"(c[0]), "+f"(c[1]), "+f"(c[2]), "+f"(c[3])
                 : "r"(a[0]), "r"(a[1]), "r"(a[2]), "r"(a[3]), "r"(b0), "r"(b1));
}
__device__ __forceinline__ void split2(float a, float b, uint32_t& hi, uint32_t& lo) {
    __nv_bfloat16 ha = __float2bfloat16_rn(a), hb = __float2bfloat16_rn(b);
    __nv_bfloat16 la = __float2bfloat16_rn(a - __bfloat162float(ha));
    __nv_bfloat16 lb = __float2bfloat16_rn(b - __bfloat162float(hb));
    hi = ((uint32_t)__bfloat16_as_ushort(hb) << 16) | __bfloat16_as_ushort(ha);
    lo = ((uint32_t)__bfloat16_as_ushort(lb) << 16) | __bfloat16_as_ushort(la);
}

// ---------------------------------------------------------------------------
// Kernel 1: scores = mask ? scale * Q K^T : -1e12
// 128x128 tile, 512 threads (16 warps = 4m x 4n, warp tile 32x32),
// FULL K=128 resident in smem (hi/lo planes), ONE barrier, and a
// register-double-buffered fragment pipeline (LDSM for kk+1 under MMA of kk).
// ---------------------------------------------------------------------------
__global__ void __launch_bounds__(512) qk_kernel(const float* __restrict__ q,
                                                 const float* __restrict__ k,
                                                 const int*   __restrict__ mask) {
    extern __shared__ __align__(16) uint8_t sm[];
    constexpr uint32_t QH = 0, QL = 34816, KH = 69632, KL = 104448;   // pitch 136 bf16
    const uint32_t sb = (uint32_t)__cvta_generic_to_shared(sm);

    const int tid  = threadIdx.x;
    const int lane = tid & 31;
    const int wid  = tid >> 5;
    const int wm   = wid & 3;
    const int wn   = wid >> 2;
    const int bh   = blockIdx.z;
    const int b    = bh >> 3;
    const int row0 = blockIdx.y << 7;
    const int col0 = blockIdx.x << 7;

    // ---- load + split Q(128x128), K(128x128) fp32 -> bf16 hi/lo planes
    const int grow = tid >> 2;
    const int gc0  = (tid & 3) << 2;
    const float* qg = q + ((size_t)bh * S_ + row0 + grow) * D_;
    const float* kg = k + ((size_t)bh * S_ + col0 + grow) * D_;

    #pragma unroll
    for (int j = 0; j < 8; ++j) {
        int c4 = gc0 + 16 * j;
        uint32_t off = 2u * ((uint32_t)grow * 136 + c4);
        float4 vq = *(const float4*)(qg + c4);
        uint32_t h0, l0, h1, l1;
        split2(vq.x, vq.y, h0, l0); split2(vq.z, vq.w, h1, l1);
        *(uint2*)(sm + QH + off) = make_uint2(h0, h1);
        *(uint2*)(sm + QL + off) = make_uint2(l0, l1);
        float4 vk = *(const float4*)(kg + c4);
        split2(vk.x, vk.y, h0, l0); split2(vk.z, vk.w, h1, l1);
        *(uint2*)(sm + KH + off) = make_uint2(h0, h1);
        *(uint2*)(sm + KL + off) = make_uint2(l0, l1);
    }
    __syncthreads();   // the ONLY barrier before the epilogue

    // ---- ldmatrix addresses
    const int lrA = lane & 15, lcA = (lane >> 4) << 3;
    const int lrB = ((lane >> 4) << 3) + (lane & 7), lcB = ((lane >> 3) & 1) << 3;
    uint32_t aAddr[2][2], bAddr[2][2];
    #pragma unroll
    for (int p = 0; p < 2; ++p) {
        #pragma unroll
        for (int mi = 0; mi < 2; ++mi)
            aAddr[p][mi] = sb + QH + p * 34816
                         + 2u * ((uint32_t)(wm * 32 + mi * 16 + lrA) * 136 + lcA);
        #pragma unroll
        for (int nt = 0; nt < 2; ++nt)
            bAddr[p][nt] = sb + KH + p * 34816
                         + 2u * ((uint32_t)(wn * 32 + nt * 16 + lrB) * 136 + lcB);
    }

    float acc[2][4][4] = {};
    uint32_t fAh[2][2][4], fAl[2][2][4], fBh[2][2][4], fBl[2][2][4];   // [set][..]

    #pragma unroll
    for (int kk = 0; kk < 8; ++kk) {
        const int cur = kk & 1;
        if (kk == 0) {   // prime set 0
            ldsm4(fAh[0][0], aAddr[0][0]); ldsm4(fAh[0][1], aAddr[0][1]);
            ldsm4(fAl[0][0], aAddr[1][0]); ldsm4(fAl[0][1], aAddr[1][1]);
            ldsm4(fBh[0][0], bAddr[0][0]); ldsm4(fBh[0][1], bAddr[0][1]);
            ldsm4(fBl[0][0], bAddr[1][0]); ldsm4(fBl[0][1], bAddr[1][1]);
        }
        if (kk < 7) {    // prefetch kk+1 fragments under this step's MMAs
            const int nxt = cur ^ 1;
            const uint32_t ko = 32u * (kk + 1);
            ldsm4(fAh[nxt][0], aAddr[0][0] + ko); ldsm4(fAh[nxt][1], aAddr[0][1] + ko);
            ldsm4(fAl[nxt][0], aAddr[1][0] + ko); ldsm4(fAl[nxt][1], aAddr[1][1] + ko);
            ldsm4(fBh[nxt][0], bAddr[0][0] + ko); ldsm4(fBh[nxt][1], bAddr[0][1] + ko);
            ldsm4(fBl[nxt][0], bAddr[1][0] + ko); ldsm4(fBl[nxt][1], bAddr[1][1] + ko);
        }
        #pragma unroll
        for (int mi = 0; mi < 2; ++mi)     // hh
            #pragma unroll
            for (int ni = 0; ni < 4; ++ni)
                mma_bf16(acc[mi][ni], fAh[cur][mi],
                         fBh[cur][ni >> 1][(ni & 1) * 2], fBh[cur][ni >> 1][(ni & 1) * 2 + 1]);
        #pragma unroll
        for (int mi = 0; mi < 2; ++mi)     // hl
            #pragma unroll
            for (int ni = 0; ni < 4; ++ni)
                mma_bf16(acc[mi][ni], fAh[cur][mi],
                         fBl[cur][ni >> 1][(ni & 1) * 2], fBl[cur][ni >> 1][(ni & 1) * 2 + 1]);
        #pragma unroll
        for (int mi = 0; mi < 2; ++mi)     // lh
            #pragma unroll
            for (int ni = 0; ni < 4; ++ni)
                mma_bf16(acc[mi][ni], fAl[cur][mi],
                         fBh[cur][ni >> 1][(ni & 1) * 2], fBh[cur][ni >> 1][(ni & 1) * 2 + 1]);
    }

    // ---- epilogue: mask + scale + store
    const float scale = 0.08838834764831845f;
    float*     srow = g_scores + (size_t)bh * S_ * S_;
    const int* mrow = mask     + (size_t)b  * S_ * S_;
    const int  rb   = row0 + wm * 32 + (lane >> 2);
    const int  cb   = col0 + wn * 32 + ((lane & 3) << 1);

    #pragma unroll
    for (int mi = 0; mi < 2; ++mi)
        #pragma unroll
        for (int h = 0; h < 2; ++h) {
            int r = rb + mi * 16 + h * 8;
            #pragma unroll
            for (int ni = 0; ni < 4; ++ni) {
                int cc = cb + ni * 8;
                int2 mk = *(const int2*)(mrow + (size_t)r * S_ + cc);
                float2 o;
                o.x = mk.x ? acc[mi][ni][2 * h]     * scale : NEG_INF_F;
                o.y = mk.y ? acc[mi][ni][2 * h + 1] * scale : NEG_INF_F;
                *(float2*)(srow + (size_t)r * S_ + cc) = o;
            }
        }
}

// ---------------------------------------------------------------------------
// Kernel 2: per-row entmax-1.5 threshold, one warp per row.
// ---------------------------------------------------------------------------
__global__ void __launch_bounds__(256) entmax_tau_kernel() {
    const int tid  = threadIdx.x;
    const int lane = tid & 31;
    const int wid  = tid >> 5;
    const size_t row = (size_t)blockIdx.x * 8 + wid;

    const float4* rowp = (const float4*)(g_scores + row * S_);

    float x[32];
    float m = -3.4e38f;
    #pragma unroll
    for (int j = 0; j < 8; ++j) {
        float4 v = rowp[lane + (j << 5)];
        x[j * 4 + 0] = v.x; x[j * 4 + 1] = v.y;
        x[j * 4 + 2] = v.z; x[j * 4 + 3] = v.w;
        m = fmaxf(m, fmaxf(fmaxf(v.x, v.y), fmaxf(v.z, v.w)));
    }
    #pragma unroll
    for (int o = 16; o; o >>= 1) m = fmaxf(m, __shfl_xor_sync(0xffffffffu, m, o));

    #pragma unroll
    for (int e = 0; e < 32; ++e) x[e] = (x[e] - m) * 0.5f;

    float tau = -1.0f;
    for (int it = 0; it < 16; ++it) {
        float s1 = 0.0f, s2 = 0.0f;
        #pragma unroll
        for (int e = 0; e < 32; ++e) {
            float t = fmaxf(x[e] - tau, 0.0f);
            s1 += t;
            s2 = fmaf(t, t, s2);
        }
        #pragma unroll
        for (int o = 16; o; o >>= 1) {
            s1 += __shfl_xor_sync(0xffffffffu, s1, o);
            s2 += __shfl_xor_sync(0xffffffffu, s2, o);
        }
        tau += (s2 - 1.0f) / (2.0f * s1);
        tau  = fminf(tau, -0.03125f);
        if (fabsf(s2 - 1.0f) < 2e-6f) break;
    }

    if (lane == 0) g_thresh[row] = m + 2.0f * tau;
}

// ---------------------------------------------------------------------------
// Kernel 3: out = P V, P = max((s-T)/2,0)^2 on the fly.
// 64(M) x 128(N=D) tile, 256 threads (2m x 4n warps), BK=32, double-buffered
// smem + distance-2 gmem register pipeline; split/STS hoisted BEFORE the MMA
// block so the barrier tail shrinks. 2 CTAs/SM.
// ---------------------------------------------------------------------------
__global__ void __launch_bounds__(256, 2) pv_kernel(const float* __restrict__ v,
                                                    float* __restrict__ out) {
    extern __shared__ __align__(16) uint8_t sm[];
    constexpr uint32_t PH = 0, PL = 5120, VH = 10240, VL = 18944, BUF = 27648;
    const uint32_t sb = (uint32_t)__cvta_generic_to_shared(sm);

    const int tid  = threadIdx.x;
    const int lane = tid & 31;
    const int wid  = tid >> 5;
    const int wm   = wid & 1;
    const int wn   = wid >> 1;
    const int bh   = blockIdx.y;
    const int row0 = blockIdx.x << 6;

    const int pr = tid >> 3;
    const int pc = (tid & 7) << 2;
    const float* pg  = g_scores + ((size_t)bh * S_ + row0) * S_;
    const float* pp0 = pg + (size_t)pr * S_ + pc;
    const float* pp1 = pg + (size_t)(pr + 32) * S_ + pc;
    const float  T0  = g_thresh[(size_t)bh * S_ + row0 + pr];
    const float  T1  = g_thresh[(size_t)bh * S_ + row0 + pr + 32];

    const int vr = tid >> 5;
    const int vc = lane << 2;
    const float* vg = v + (size_t)bh * S_ * D_;

    float4 Pr[2][2], Vr[2][4];

    auto load_chunk = [&](int c, int s) {
        Pr[s][0] = *(const float4*)(pp0 + c * 32);
        Pr[s][1] = *(const float4*)(pp1 + c * 32);
        #pragma unroll
        for (int i = 0; i < 4; ++i)
            Vr[s][i] = *(const float4*)(vg + (size_t)(c * 32 + vr + 8 * i) * D_ + vc);
    };
    auto store_chunk = [&](int s, int buf) {
        uint8_t* B = sm + (uint32_t)buf * BUF;
        #pragma unroll
        for (int i = 0; i < 2; ++i) {
            float T = i ? T1 : T0;
            float4 sc = Pr[s][i];
            float t0 = fmaxf((sc.x - T) * 0.5f, 0.0f);
            float t1 = fmaxf((sc.y - T) * 0.5f, 0.0f);
            float t2 = fmaxf((sc.z - T) * 0.5f, 0.0f);
            float t3 = fmaxf((sc.w - T) * 0.5f, 0.0f);
            uint32_t h0, l0, h1, l1;
            split2(t0 * t0, t1 * t1, h0, l0);
            split2(t2 * t2, t3 * t3, h1, l1);
            uint32_t off = 2u * ((uint32_t)(pr + 32 * i) * 40 + pc);
            *(uint2*)(B + PH + off) = make_uint2(h0, h1);
            *(uint2*)(B + PL + off) = make_uint2(l0, l1);
        }
        #pragma unroll
        for (int i = 0; i < 4; ++i) {
            float4 vv = Vr[s][i];
            uint32_t h0, l0, h1, l1;
            split2(vv.x, vv.y, h0, l0);
            split2(vv.z, vv.w, h1, l1);
            uint32_t off = 2u * ((uint32_t)(vr + 8 * i) * 136 + vc);
            *(uint2*)(B + VH + off) = make_uint2(h0, h1);
            *(uint2*)(B + VL + off) = make_uint2(l0, l1);
        }
    };

    const int lrA = lane & 15, lcA = (lane >> 4) << 3;
    const int lrB = ((lane >> 3) & 1) * 8 + (lane & 7);
    const int lcB = (lane >> 4) << 3;
    uint32_t aAddr[2][2], bAddr[2][2];
    #pragma unroll
    for (int p = 0; p < 2; ++p) {
        #pragma unroll
        for (int mi = 0; mi < 2; ++mi)
            aAddr[p][mi] = sb + PH + p * 5120
                         + 2u * ((uint32_t)(wm * 32 + mi * 16 + lrA) * 40 + lcA);
        #pragma unroll
        for (int nt = 0; nt < 2; ++nt)
            bAddr[p][nt] = sb + VH + p * 8704
                         + 2u * ((uint32_t)lrB * 136 + wn * 32 + nt * 16 + lcB);
    }

    // ---- pipeline preamble
    load_chunk(0, 0);
    store_chunk(0, 0);
    load_chunk(1, 1);
    __syncthreads();

    float acc[2][4][4] = {};
    constexpr int NC = S_ / 32;    // 32 chunks

    #pragma unroll 2
    for (int c = 0; c < NC; ++c) {
        const int buf = c & 1;
        if (c + 2 < NC) load_chunk(c + 2, buf);        // gmem, distance 2
        if (c + 1 < NC) store_chunk((c + 1) & 1, buf ^ 1);  // split+STS before MMAs

        const uint32_t bo = (uint32_t)buf * BUF;
        #pragma unroll
        for (int kk = 0; kk < 2; ++kk) {
            const uint32_t koA = 32u * kk;
            const uint32_t koB = 4352u * kk;
            uint32_t Ah[2][4], Al[2][4], Bh[2][4], Bl[2][4];
            ldsm4(Ah[0], aAddr[0][0] + bo + koA);
            ldsm4(Ah[1], aAddr[0][1] + bo + koA);
            ldsm4(Al[0], aAddr[1][0] + bo + koA);
            ldsm4(Al[1], aAddr[1][1] + bo + koA);
            ldsm4t(Bh[0], bAddr[0][0] + bo + koB);
            ldsm4t(Bh[1], bAddr[0][1] + bo + koB);
            ldsm4t(Bl[0], bAddr[1][0] + bo + koB);
            ldsm4t(Bl[1], bAddr[1][1] + bo + koB);
            #pragma unroll
            for (int mi = 0; mi < 2; ++mi)
                #pragma unroll
                for (int ni = 0; ni < 4; ++ni)
                    mma_bf16(acc[mi][ni], Ah[mi], Bh[ni >> 1][(ni & 1) * 2], Bh[ni >> 1][(ni & 1) * 2 + 1]);
            #pragma unroll
            for (int mi = 0; mi < 2; ++mi)
                #pragma unroll
                for (int ni = 0; ni < 4; ++ni)
                    mma_bf16(acc[mi][ni], Ah[mi], Bl[ni >> 1][(ni & 1) * 2], Bl[ni >> 1][(ni & 1) * 2 + 1]);
            #pragma unroll
            for (int mi = 0; mi < 2; ++mi)
                #pragma unroll
                for (int ni = 0; ni < 4; ++ni)
                    mma_bf16(acc[mi][ni], Al[mi], Bh[ni >> 1][(ni & 1) * 2], Bh[ni >> 1][(ni & 1) * 2 + 1]);
        }
        __syncthreads();
    }

    // ---- epilogue
    const int rb = row0 + wm * 32 + (lane >> 2);
    const int cb = wn * 32 + ((lane & 3) << 1);
    #pragma unroll
    for (int mi = 0; mi < 2; ++mi)
        #pragma unroll
        for (int h = 0; h < 2; ++h) {
            int r = rb + mi * 16 + h * 8;
            #pragma unroll
            for (int ni = 0; ni < 4; ++ni) {
                float2 o = make_float2(acc[mi][ni][2 * h], acc[mi][ni][2 * h + 1]);
                *(float2*)(out + ((size_t)bh * S_ + r) * D_ + cb + ni * 8) = o;
            }
        }
}

// ---------------------------------------------------------------------------
extern "C" void kernel_launch(void* const* d_in, const int* in_sizes, int n_in,
                              void* d_out, int out_size) {
    (void)in_sizes; (void)n_in; (void)out_size;
    const float* q    = (const float*)d_in[0];
    const float* k    = (const float*)d_in[1];
    const float* v    = (const float*)d_in[2];
    const int*   mask = (const int*)d_in[3];
    float*       out  = (float*)d_out;

    constexpr int QK_SMEM = 139264;
    constexpr int PV_SMEM = 55296;
    cudaFuncSetAttribute(qk_kernel, cudaFuncAttributeMaxDynamicSharedMemorySize, QK_SMEM);
    cudaFuncSetAttribute(pv_kernel, cudaFuncAttributeMaxDynamicSharedMemorySize, PV_SMEM);

    qk_kernel<<<dim3(8, 8, BH_), 512, QK_SMEM>>>(q, k, mask);
    entmax_tau_kernel<<<BH_ * S_ / 8, 256>>>();
    pv_kernel<<<dim3(16, BH_), 256, PV_SMEM>>>(v, out);
}

// round 9
// speedup vs baseline: 1.0731x; 1.0731x over previous
#include <cuda_runtime.h>
#include <cuda_bf16.h>
#include <cstdint>

#define NEG_INF_F (-1.0e12f)

constexpr int S_  = 1024;
constexpr int D_  = 128;
constexpr int BH_ = 32;   // B*H

static __device__ float g_scores[(size_t)BH_ * S_ * S_];
static __device__ float g_thresh[(size_t)BH_ * S_];   // rowmax + 2*tau

// ---------------------------------------------------------------------------
// PTX helpers
// ---------------------------------------------------------------------------
__device__ __forceinline__ void ldsm4(uint32_t* r, uint32_t addr) {
    asm volatile("ldmatrix.sync.aligned.m8n8.x4.shared.b16 {%0,%1,%2,%3}, [%4];\n"
                 : "=r"(r[0]), "=r"(r[1]), "=r"(r[2]), "=r"(r[3]) : "r"(addr));
}
__device__ __forceinline__ void ldsm4t(uint32_t* r, uint32_t addr) {
    asm volatile("ldmatrix.sync.aligned.m8n8.x4.trans.shared.b16 {%0,%1,%2,%3}, [%4];\n"
                 : "=r"(r[0]), "=r"(r[1]), "=r"(r[2]), "=r"(r[3]) : "r"(addr));
}
__device__ __forceinline__ void mma_bf16(float* c, const uint32_t* a,
                                         uint32_t b0, uint32_t b1) {
    asm volatile("mma.sync.aligned.m16n8k16.row.col.f32.bf16.bf16.f32 "
                 "{%0,%1,%2,%3}, {%4,%5,%6,%7}, {%8,%9}, {%0,%1,%2,%3};\n"
                 : "+f"(c[0]), "+f"(c[1]), "+f"(c[2]), "+f"(c[3])
                 : "r"(a[0]), "r"(a[1]), "r"(a[2]), "r"(a[3]), "r"(b0), "r"(b1));
}
__device__ __forceinline__ void split2(float a, float b, uint32_t& hi, uint32_t& lo) {
    __nv_bfloat16 ha = __float2bfloat16_rn(a), hb = __float2bfloat16_rn(b);
    __nv_bfloat16 la = __float2bfloat16_rn(a - __bfloat162float(ha));
    __nv_bfloat16 lb = __float2bfloat16_rn(b - __bfloat162float(hb));
    hi = ((uint32_t)__bfloat16_as_ushort(hb) << 16) | __bfloat16_as_ushort(ha);
    lo = ((uint32_t)__bfloat16_as_ushort(lb) << 16) | __bfloat16_as_ushort(la);
}

// ---------------------------------------------------------------------------
// Kernel 1: scores = mask ? scale * Q K^T : -1e12
// 64(M) x 128(N) tile, 256 threads (8 warps = 2m x 4n, warp tile 32x32),
// BK=32 over D=128, double-buffered smem, distance-2 register pipeline,
// 2 CTAs/SM. (Mirror of pv_kernel's shape — measured ~35% more efficient.)
// ---------------------------------------------------------------------------
__global__ void __launch_bounds__(256, 2) qk_kernel(const float* __restrict__ q,
                                                    const float* __restrict__ k,
                                                    const int*   __restrict__ mask) {
    extern __shared__ __align__(16) uint8_t sm[];
    // per buffer: QH 64x40, QL, KH 128x40, KL   (pitch 40 bf16 = 80B)
    constexpr uint32_t QH = 0, QL = 5120, KH = 10240, KL = 20480, BUF = 30720;
    const uint32_t sb = (uint32_t)__cvta_generic_to_shared(sm);

    const int tid  = threadIdx.x;
    const int lane = tid & 31;
    const int wid  = tid >> 5;
    const int wm   = wid & 1;          // 2 m-slabs of 32
    const int wn   = wid >> 1;         // 4 n-slabs of 32
    const int bh   = blockIdx.z;
    const int b    = bh >> 3;
    const int row0 = blockIdx.x << 6;  // 64 query rows
    const int col0 = blockIdx.y << 7;  // 128 key rows

    // gmem mapping: rows pr (+32i), cols pc..pc+3, chunk offset c*32
    const int pr = tid >> 3;           // 0..31
    const int pc = (tid & 7) << 2;     // 0..28
    const float* qp0 = q + ((size_t)bh * S_ + row0 + pr) * D_ + pc;
    const float* qp1 = qp0 + (size_t)32 * D_;
    const float* kp  = k + ((size_t)bh * S_ + col0 + pr) * D_ + pc;

    float4 Qr[2][2], Kr[2][4];

    auto load_chunk = [&](int c, int s) {
        Qr[s][0] = *(const float4*)(qp0 + c * 32);
        Qr[s][1] = *(const float4*)(qp1 + c * 32);
        #pragma unroll
        for (int i = 0; i < 4; ++i)
            Kr[s][i] = *(const float4*)(kp + (size_t)(32 * i) * D_ + c * 32);
    };
    auto store_chunk = [&](int s, int buf) {
        uint8_t* B = sm + (uint32_t)buf * BUF;
        #pragma unroll
        for (int i = 0; i < 2; ++i) {
            float4 vq = Qr[s][i];
            uint32_t h0, l0, h1, l1;
            split2(vq.x, vq.y, h0, l0);
            split2(vq.z, vq.w, h1, l1);
            uint32_t off = 2u * ((uint32_t)(pr + 32 * i) * 40 + pc);
            *(uint2*)(B + QH + off) = make_uint2(h0, h1);
            *(uint2*)(B + QL + off) = make_uint2(l0, l1);
        }
        #pragma unroll
        for (int i = 0; i < 4; ++i) {
            float4 vk = Kr[s][i];
            uint32_t h0, l0, h1, l1;
            split2(vk.x, vk.y, h0, l0);
            split2(vk.z, vk.w, h1, l1);
            uint32_t off = 2u * ((uint32_t)(pr + 32 * i) * 40 + pc);
            *(uint2*)(B + KH + off) = make_uint2(h0, h1);
            *(uint2*)(B + KL + off) = make_uint2(l0, l1);
        }
    };

    // ldmatrix addresses (buffer 0; add buf*BUF)
    const int lrA = lane & 15, lcA = (lane >> 4) << 3;
    const int lrB = ((lane >> 4) << 3) + (lane & 7), lcB = ((lane >> 3) & 1) << 3;
    uint32_t aAddr[2][2], bAddr[2][2];
    #pragma unroll
    for (int p = 0; p < 2; ++p) {
        #pragma unroll
        for (int mi = 0; mi < 2; ++mi)
            aAddr[p][mi] = sb + QH + p * 5120
                         + 2u * ((uint32_t)(wm * 32 + mi * 16 + lrA) * 40 + lcA);
        #pragma unroll
        for (int nt = 0; nt < 2; ++nt)
            bAddr[p][nt] = sb + KH + p * 10240
                         + 2u * ((uint32_t)(wn * 32 + nt * 16 + lrB) * 40 + lcB);
    }

    // ---- pipeline preamble
    load_chunk(0, 0);
    store_chunk(0, 0);
    load_chunk(1, 1);
    __syncthreads();

    float acc[2][4][4] = {};
    constexpr int NC = D_ / 32;    // 4 chunks

    #pragma unroll
    for (int c = 0; c < NC; ++c) {
        const int buf = c & 1;
        if (c + 2 < NC) load_chunk(c + 2, buf);   // reg set free: chunk c in smem

        const uint32_t bo = (uint32_t)buf * BUF;
        #pragma unroll
        for (int kk = 0; kk < 2; ++kk) {
            const uint32_t ko = 32u * kk;
            uint32_t Ah[2][4], Al[2][4], Bh[2][4], Bl[2][4];
            ldsm4(Ah[0], aAddr[0][0] + bo + ko);
            ldsm4(Ah[1], aAddr[0][1] + bo + ko);
            ldsm4(Al[0], aAddr[1][0] + bo + ko);
            ldsm4(Al[1], aAddr[1][1] + bo + ko);
            ldsm4(Bh[0], bAddr[0][0] + bo + ko);
            ldsm4(Bh[1], bAddr[0][1] + bo + ko);
            ldsm4(Bl[0], bAddr[1][0] + bo + ko);
            ldsm4(Bl[1], bAddr[1][1] + bo + ko);
            #pragma unroll
            for (int mi = 0; mi < 2; ++mi)
                #pragma unroll
                for (int ni = 0; ni < 4; ++ni)
                    mma_bf16(acc[mi][ni], Ah[mi], Bh[ni >> 1][(ni & 1) * 2], Bh[ni >> 1][(ni & 1) * 2 + 1]);
            #pragma unroll
            for (int mi = 0; mi < 2; ++mi)
                #pragma unroll
                for (int ni = 0; ni < 4; ++ni)
                    mma_bf16(acc[mi][ni], Ah[mi], Bl[ni >> 1][(ni & 1) * 2], Bl[ni >> 1][(ni & 1) * 2 + 1]);
            #pragma unroll
            for (int mi = 0; mi < 2; ++mi)
                #pragma unroll
                for (int ni = 0; ni < 4; ++ni)
                    mma_bf16(acc[mi][ni], Al[mi], Bh[ni >> 1][(ni & 1) * 2], Bh[ni >> 1][(ni & 1) * 2 + 1]);
        }

        if (c + 1 < NC) store_chunk((c + 1) & 1, (c + 1) & 1);
        __syncthreads();
    }

    // ---- epilogue: mask + scale + store
    const float scale = 0.08838834764831845f;
    float*     srow = g_scores + (size_t)bh * S_ * S_;
    const int* mrow = mask     + (size_t)b  * S_ * S_;
    const int  rb   = row0 + wm * 32 + (lane >> 2);
    const int  cb   = col0 + wn * 32 + ((lane & 3) << 1);

    #pragma unroll
    for (int mi = 0; mi < 2; ++mi)
        #pragma unroll
        for (int h = 0; h < 2; ++h) {
            int r = rb + mi * 16 + h * 8;
            #pragma unroll
            for (int ni = 0; ni < 4; ++ni) {
                int cc = cb + ni * 8;
                int2 mk = *(const int2*)(mrow + (size_t)r * S_ + cc);
                float2 o;
                o.x = mk.x ? acc[mi][ni][2 * h]     * scale : NEG_INF_F;
                o.y = mk.y ? acc[mi][ni][2 * h + 1] * scale : NEG_INF_F;
                *(float2*)(srow + (size_t)r * S_ + cc) = o;
            }
        }
}

// ---------------------------------------------------------------------------
// Kernel 2: per-row entmax-1.5 threshold, one warp per row, 512-thread blocks.
// ---------------------------------------------------------------------------
__global__ void __launch_bounds__(512) entmax_tau_kernel() {
    const int tid  = threadIdx.x;
    const int lane = tid & 31;
    const int wid  = tid >> 5;
    const size_t row = (size_t)blockIdx.x * 16 + wid;

    const float4* rowp = (const float4*)(g_scores + row * S_);

    float x[32];
    float m = -3.4e38f;
    #pragma unroll
    for (int j = 0; j < 8; ++j) {
        float4 v = rowp[lane + (j << 5)];
        x[j * 4 + 0] = v.x; x[j * 4 + 1] = v.y;
        x[j * 4 + 2] = v.z; x[j * 4 + 3] = v.w;
        m = fmaxf(m, fmaxf(fmaxf(v.x, v.y), fmaxf(v.z, v.w)));
    }
    #pragma unroll
    for (int o = 16; o; o >>= 1) m = fmaxf(m, __shfl_xor_sync(0xffffffffu, m, o));

    #pragma unroll
    for (int e = 0; e < 32; ++e) x[e] = (x[e] - m) * 0.5f;

    float tau = -1.0f;
    for (int it = 0; it < 16; ++it) {
        float s1 = 0.0f, s2 = 0.0f;
        #pragma unroll
        for (int e = 0; e < 32; ++e) {
            float t = fmaxf(x[e] - tau, 0.0f);
            s1 += t;
            s2 = fmaf(t, t, s2);
        }
        #pragma unroll
        for (int o = 16; o; o >>= 1) {
            s1 += __shfl_xor_sync(0xffffffffu, s1, o);
            s2 += __shfl_xor_sync(0xffffffffu, s2, o);
        }
        tau += (s2 - 1.0f) / (2.0f * s1);
        tau  = fminf(tau, -0.03125f);
        if (fabsf(s2 - 1.0f) < 2e-6f) break;
    }

    if (lane == 0) g_thresh[row] = m + 2.0f * tau;
}

// ---------------------------------------------------------------------------
// Kernel 3: out = P V, P = max((s-T)/2,0)^2 on the fly. (Round-7 ordering.)
// 64(M) x 128(N=D) tile, 256 threads, BK=32, double-buffered, 2 CTAs/SM.
// ---------------------------------------------------------------------------
__global__ void __launch_bounds__(256, 2) pv_kernel(const float* __restrict__ v,
                                                    float* __restrict__ out) {
    extern __shared__ __align__(16) uint8_t sm[];
    constexpr uint32_t PH = 0, PL = 5120, VH = 10240, VL = 18944, BUF = 27648;
    const uint32_t sb = (uint32_t)__cvta_generic_to_shared(sm);

    const int tid  = threadIdx.x;
    const int lane = tid & 31;
    const int wid  = tid >> 5;
    const int wm   = wid & 1;
    const int wn   = wid >> 1;
    const int bh   = blockIdx.y;
    const int row0 = blockIdx.x << 6;

    const int pr = tid >> 3;
    const int pc = (tid & 7) << 2;
    const float* pg  = g_scores + ((size_t)bh * S_ + row0) * S_;
    const float* pp0 = pg + (size_t)pr * S_ + pc;
    const float* pp1 = pg + (size_t)(pr + 32) * S_ + pc;
    const float  T0  = g_thresh[(size_t)bh * S_ + row0 + pr];
    const float  T1  = g_thresh[(size_t)bh * S_ + row0 + pr + 32];

    const int vr = tid >> 5;
    const int vc = lane << 2;
    const float* vg = v + (size_t)bh * S_ * D_;

    float4 Pr[2][2], Vr[2][4];

    auto load_chunk = [&](int c, int s) {
        Pr[s][0] = *(const float4*)(pp0 + c * 32);
        Pr[s][1] = *(const float4*)(pp1 + c * 32);
        #pragma unroll
        for (int i = 0; i < 4; ++i)
            Vr[s][i] = *(const float4*)(vg + (size_t)(c * 32 + vr + 8 * i) * D_ + vc);
    };
    auto store_chunk = [&](int s, int buf) {
        uint8_t* B = sm + (uint32_t)buf * BUF;
        #pragma unroll
        for (int i = 0; i < 2; ++i) {
            float T = i ? T1 : T0;
            float4 sc = Pr[s][i];
            float t0 = fmaxf((sc.x - T) * 0.5f, 0.0f);
            float t1 = fmaxf((sc.y - T) * 0.5f, 0.0f);
            float t2 = fmaxf((sc.z - T) * 0.5f, 0.0f);
            float t3 = fmaxf((sc.w - T) * 0.5f, 0.0f);
            uint32_t h0, l0, h1, l1;
            split2(t0 * t0, t1 * t1, h0, l0);
            split2(t2 * t2, t3 * t3, h1, l1);
            uint32_t off = 2u * ((uint32_t)(pr + 32 * i) * 40 + pc);
            *(uint2*)(B + PH + off) = make_uint2(h0, h1);
            *(uint2*)(B + PL + off) = make_uint2(l0, l1);
        }
        #pragma unroll
        for (int i = 0; i < 4; ++i) {
            float4 vv = Vr[s][i];
            uint32_t h0, l0, h1, l1;
            split2(vv.x, vv.y, h0, l0);
            split2(vv.z, vv.w, h1, l1);
            uint32_t off = 2u * ((uint32_t)(vr + 8 * i) * 136 + vc);
            *(uint2*)(B + VH + off) = make_uint2(h0, h1);
            *(uint2*)(B + VL + off) = make_uint2(l0, l1);
        }
    };

    const int lrA = lane & 15, lcA = (lane >> 4) << 3;
    const int lrB = ((lane >> 3) & 1) * 8 + (lane & 7);
    const int lcB = (lane >> 4) << 3;
    uint32_t aAddr[2][2], bAddr[2][2];
    #pragma unroll
    for (int p = 0; p < 2; ++p) {
        #pragma unroll
        for (int mi = 0; mi < 2; ++mi)
            aAddr[p][mi] = sb + PH + p * 5120
                         + 2u * ((uint32_t)(wm * 32 + mi * 16 + lrA) * 40 + lcA);
        #pragma unroll
        for (int nt = 0; nt < 2; ++nt)
            bAddr[p][nt] = sb + VH + p * 8704
                         + 2u * ((uint32_t)lrB * 136 + wn * 32 + nt * 16 + lcB);
    }

    // ---- pipeline preamble
    load_chunk(0, 0);
    store_chunk(0, 0);
    load_chunk(1, 1);
    __syncthreads();

    float acc[2][4][4] = {};
    constexpr int NC = S_ / 32;    // 32 chunks

    #pragma unroll 2
    for (int c = 0; c < NC; ++c) {
        const int buf = c & 1;
        if (c + 2 < NC) load_chunk(c + 2, buf);

        const uint32_t bo = (uint32_t)buf * BUF;
        #pragma unroll
        for (int kk = 0; kk < 2; ++kk) {
            const uint32_t koA = 32u * kk;
            const uint32_t koB = 4352u * kk;
            uint32_t Ah[2][4], Al[2][4], Bh[2][4], Bl[2][4];
            ldsm4(Ah[0], aAddr[0][0] + bo + koA);
            ldsm4(Ah[1], aAddr[0][1] + bo + koA);
            ldsm4(Al[0], aAddr[1][0] + bo + koA);
            ldsm4(Al[1], aAddr[1][1] + bo + koA);
            ldsm4t(Bh[0], bAddr[0][0] + bo + koB);
            ldsm4t(Bh[1], bAddr[0][1] + bo + koB);
            ldsm4t(Bl[0], bAddr[1][0] + bo + koB);
            ldsm4t(Bl[1], bAddr[1][1] + bo + koB);
            #pragma unroll
            for (int mi = 0; mi < 2; ++mi)
                #pragma unroll
                for (int ni = 0; ni < 4; ++ni)
                    mma_bf16(acc[mi][ni], Ah[mi], Bh[ni >> 1][(ni & 1) * 2], Bh[ni >> 1][(ni & 1) * 2 + 1]);
            #pragma unroll
            for (int mi = 0; mi < 2; ++mi)
                #pragma unroll
                for (int ni = 0; ni < 4; ++ni)
                    mma_bf16(acc[mi][ni], Ah[mi], Bl[ni >> 1][(ni & 1) * 2], Bl[ni >> 1][(ni & 1) * 2 + 1]);
            #pragma unroll
            for (int mi = 0; mi < 2; ++mi)
                #pragma unroll
                for (int ni = 0; ni < 4; ++ni)
                    mma_bf16(acc[mi][ni], Al[mi], Bh[ni >> 1][(ni & 1) * 2], Bh[ni >> 1][(ni & 1) * 2 + 1]);
        }

        if (c + 1 < NC) store_chunk((c + 1) & 1, (c + 1) & 1);
        __syncthreads();
    }

    // ---- epilogue
    const int rb = row0 + wm * 32 + (lane >> 2);
    const int cb = wn * 32 + ((lane & 3) << 1);
    #pragma unroll
    for (int mi = 0; mi < 2; ++mi)
        #pragma unroll
        for (int h = 0; h < 2; ++h) {
            int r = rb + mi * 16 + h * 8;
            #pragma unroll
            for (int ni = 0; ni < 4; ++ni) {
                float2 o = make_float2(acc[mi][ni][2 * h], acc[mi][ni][2 * h + 1]);
                *(float2*)(out + ((size_t)bh * S_ + r) * D_ + cb + ni * 8) = o;
            }
        }
}

// ---------------------------------------------------------------------------
extern "C" void kernel_launch(void* const* d_in, const int* in_sizes, int n_in,
                              void* d_out, int out_size) {
    (void)in_sizes; (void)n_in; (void)out_size;
    const float* q    = (const float*)d_in[0];
    const float* k    = (const float*)d_in[1];
    const float* v    = (const float*)d_in[2];
    const int*   mask = (const int*)d_in[3];
    float*       out  = (float*)d_out;

    constexpr int QK_SMEM = 61440;   // 2 buffers of 30720B
    constexpr int PV_SMEM = 55296;   // 2 buffers of 27648B
    cudaFuncSetAttribute(qk_kernel, cudaFuncAttributeMaxDynamicSharedMemorySize, QK_SMEM);
    cudaFuncSetAttribute(pv_kernel, cudaFuncAttributeMaxDynamicSharedMemorySize, PV_SMEM);

    qk_kernel<<<dim3(16, 8, BH_), 256, QK_SMEM>>>(q, k, mask);
    entmax_tau_kernel<<<BH_ * S_ / 16, 512>>>();
    pv_kernel<<<dim3(16, BH_), 256, PV_SMEM>>>(v, out);
}

// round 10
// speedup vs baseline: 1.3639x; 1.2710x over previous
#include <cuda_runtime.h>
#include <cuda_bf16.h>
#include <cstdint>

#define NEG_INF_F (-1.0e12f)

constexpr int S_  = 1024;
constexpr int D_  = 128;
constexpr int BH_ = 32;   // B*H

static __device__ float g_scores[(size_t)BH_ * S_ * S_];          // masked scaled scores
static __device__ float g_pvals[(size_t)BH_ * S_ * S_];           // compacted probs
static __device__ int   g_pidx [(size_t)BH_ * S_ * S_];           // compacted key idx
static __device__ int   g_count[(size_t)BH_ * S_];                // support per row

// ---------------------------------------------------------------------------
// PTX helpers
// ---------------------------------------------------------------------------
__device__ __forceinline__ void ldsm4(uint32_t* r, uint32_t addr) {
    asm volatile("ldmatrix.sync.aligned.m8n8.x4.shared.b16 {%0,%1,%2,%3}, [%4];\n"
                 : "=r"(r[0]), "=r"(r[1]), "=r"(r[2]), "=r"(r[3]) : "r"(addr));
}
__device__ __forceinline__ void mma_bf16(float* c, const uint32_t* a,
                                         uint32_t b0, uint32_t b1) {
    asm volatile("mma.sync.aligned.m16n8k16.row.col.f32.bf16.bf16.f32 "
                 "{%0,%1,%2,%3}, {%4,%5,%6,%7}, {%8,%9}, {%0,%1,%2,%3};\n"
                 : "+f"(c[0]), "+f"(c[1]), "+f"(c[2]), "+f"(c[3])
                 : "r"(a[0]), "r"(a[1]), "r"(a[2]), "r"(a[3]), "r"(b0), "r"(b1));
}
__device__ __forceinline__ void split2(float a, float b, uint32_t& hi, uint32_t& lo) {
    __nv_bfloat16 ha = __float2bfloat16_rn(a), hb = __float2bfloat16_rn(b);
    __nv_bfloat16 la = __float2bfloat16_rn(a - __bfloat162float(ha));
    __nv_bfloat16 lb = __float2bfloat16_rn(b - __bfloat162float(hb));
    hi = ((uint32_t)__bfloat16_as_ushort(hb) << 16) | __bfloat16_as_ushort(ha);
    lo = ((uint32_t)__bfloat16_as_ushort(lb) << 16) | __bfloat16_as_ushort(la);
}

// ---------------------------------------------------------------------------
// Kernel 1: scores = mask ? scale * Q K^T : -1e12   (unchanged from round 9)
// 64x128 tile, 256 threads (2m x 4n warps, 32x32 warp tile), BK=32,
// double-buffered smem, distance-2 register pipeline, 2 CTAs/SM.
// ---------------------------------------------------------------------------
__global__ void __launch_bounds__(256, 2) qk_kernel(const float* __restrict__ q,
                                                    const float* __restrict__ k,
                                                    const int*   __restrict__ mask) {
    extern __shared__ __align__(16) uint8_t sm[];
    constexpr uint32_t QH = 0, QL = 5120, KH = 10240, KL = 20480, BUF = 30720;
    const uint32_t sb = (uint32_t)__cvta_generic_to_shared(sm);

    const int tid  = threadIdx.x;
    const int lane = tid & 31;
    const int wid  = tid >> 5;
    const int wm   = wid & 1;
    const int wn   = wid >> 1;
    const int bh   = blockIdx.z;
    const int b    = bh >> 3;
    const int row0 = blockIdx.x << 6;
    const int col0 = blockIdx.y << 7;

    const int pr = tid >> 3;
    const int pc = (tid & 7) << 2;
    const float* qp0 = q + ((size_t)bh * S_ + row0 + pr) * D_ + pc;
    const float* qp1 = qp0 + (size_t)32 * D_;
    const float* kp  = k + ((size_t)bh * S_ + col0 + pr) * D_ + pc;

    float4 Qr[2][2], Kr[2][4];

    auto load_chunk = [&](int c, int s) {
        Qr[s][0] = *(const float4*)(qp0 + c * 32);
        Qr[s][1] = *(const float4*)(qp1 + c * 32);
        #pragma unroll
        for (int i = 0; i < 4; ++i)
            Kr[s][i] = *(const float4*)(kp + (size_t)(32 * i) * D_ + c * 32);
    };
    auto store_chunk = [&](int s, int buf) {
        uint8_t* B = sm + (uint32_t)buf * BUF;
        #pragma unroll
        for (int i = 0; i < 2; ++i) {
            float4 vq = Qr[s][i];
            uint32_t h0, l0, h1, l1;
            split2(vq.x, vq.y, h0, l0);
            split2(vq.z, vq.w, h1, l1);
            uint32_t off = 2u * ((uint32_t)(pr + 32 * i) * 40 + pc);
            *(uint2*)(B + QH + off) = make_uint2(h0, h1);
            *(uint2*)(B + QL + off) = make_uint2(l0, l1);
        }
        #pragma unroll
        for (int i = 0; i < 4; ++i) {
            float4 vk = Kr[s][i];
            uint32_t h0, l0, h1, l1;
            split2(vk.x, vk.y, h0, l0);
            split2(vk.z, vk.w, h1, l1);
            uint32_t off = 2u * ((uint32_t)(pr + 32 * i) * 40 + pc);
            *(uint2*)(B + KH + off) = make_uint2(h0, h1);
            *(uint2*)(B + KL + off) = make_uint2(l0, l1);
        }
    };

    const int lrA = lane & 15, lcA = (lane >> 4) << 3;
    const int lrB = ((lane >> 4) << 3) + (lane & 7), lcB = ((lane >> 3) & 1) << 3;
    uint32_t aAddr[2][2], bAddr[2][2];
    #pragma unroll
    for (int p = 0; p < 2; ++p) {
        #pragma unroll
        for (int mi = 0; mi < 2; ++mi)
            aAddr[p][mi] = sb + QH + p * 5120
                         + 2u * ((uint32_t)(wm * 32 + mi * 16 + lrA) * 40 + lcA);
        #pragma unroll
        for (int nt = 0; nt < 2; ++nt)
            bAddr[p][nt] = sb + KH + p * 10240
                         + 2u * ((uint32_t)(wn * 32 + nt * 16 + lrB) * 40 + lcB);
    }

    load_chunk(0, 0);
    store_chunk(0, 0);
    load_chunk(1, 1);
    __syncthreads();

    float acc[2][4][4] = {};
    constexpr int NC = D_ / 32;

    #pragma unroll
    for (int c = 0; c < NC; ++c) {
        const int buf = c & 1;
        if (c + 2 < NC) load_chunk(c + 2, buf);

        const uint32_t bo = (uint32_t)buf * BUF;
        #pragma unroll
        for (int kk = 0; kk < 2; ++kk) {
            const uint32_t ko = 32u * kk;
            uint32_t Ah[2][4], Al[2][4], Bh[2][4], Bl[2][4];
            ldsm4(Ah[0], aAddr[0][0] + bo + ko);
            ldsm4(Ah[1], aAddr[0][1] + bo + ko);
            ldsm4(Al[0], aAddr[1][0] + bo + ko);
            ldsm4(Al[1], aAddr[1][1] + bo + ko);
            ldsm4(Bh[0], bAddr[0][0] + bo + ko);
            ldsm4(Bh[1], bAddr[0][1] + bo + ko);
            ldsm4(Bl[0], bAddr[1][0] + bo + ko);
            ldsm4(Bl[1], bAddr[1][1] + bo + ko);
            #pragma unroll
            for (int mi = 0; mi < 2; ++mi)
                #pragma unroll
                for (int ni = 0; ni < 4; ++ni)
                    mma_bf16(acc[mi][ni], Ah[mi], Bh[ni >> 1][(ni & 1) * 2], Bh[ni >> 1][(ni & 1) * 2 + 1]);
            #pragma unroll
            for (int mi = 0; mi < 2; ++mi)
                #pragma unroll
                for (int ni = 0; ni < 4; ++ni)
                    mma_bf16(acc[mi][ni], Ah[mi], Bl[ni >> 1][(ni & 1) * 2], Bl[ni >> 1][(ni & 1) * 2 + 1]);
            #pragma unroll
            for (int mi = 0; mi < 2; ++mi)
                #pragma unroll
                for (int ni = 0; ni < 4; ++ni)
                    mma_bf16(acc[mi][ni], Al[mi], Bh[ni >> 1][(ni & 1) * 2], Bh[ni >> 1][(ni & 1) * 2 + 1]);
        }

        if (c + 1 < NC) store_chunk((c + 1) & 1, (c + 1) & 1);
        __syncthreads();
    }

    const float scale = 0.08838834764831845f;
    float*     srow = g_scores + (size_t)bh * S_ * S_;
    const int* mrow = mask     + (size_t)b  * S_ * S_;
    const int  rb   = row0 + wm * 32 + (lane >> 2);
    const int  cb   = col0 + wn * 32 + ((lane & 3) << 1);

    #pragma unroll
    for (int mi = 0; mi < 2; ++mi)
        #pragma unroll
        for (int h = 0; h < 2; ++h) {
            int r = rb + mi * 16 + h * 8;
            #pragma unroll
            for (int ni = 0; ni < 4; ++ni) {
                int cc = cb + ni * 8;
                int2 mk = *(const int2*)(mrow + (size_t)r * S_ + cc);
                float2 o;
                o.x = mk.x ? acc[mi][ni][2 * h]     * scale : NEG_INF_F;
                o.y = mk.y ? acc[mi][ni][2 * h + 1] * scale : NEG_INF_F;
                *(float2*)(srow + (size_t)r * S_ + cc) = o;
            }
        }
}

// ---------------------------------------------------------------------------
// Kernel 2: per-row entmax-1.5 + SUPPORT COMPACTION, one warp per row.
// Newton for tau, then emit (p, idx) for every element with x > tau via
// ballot/popc warp scan. Exact: all support entries are written (cap = 1024
// = row length, so even degenerate near-uniform rows are handled exactly).
// ---------------------------------------------------------------------------
__global__ void __launch_bounds__(512) entmax_kernel() {
    const int tid  = threadIdx.x;
    const int lane = tid & 31;
    const int wid  = tid >> 5;
    const size_t row = (size_t)blockIdx.x * 16 + wid;

    const float4* rowp = (const float4*)(g_scores + row * S_);

    float x[32];
    float m = -3.4e38f;
    #pragma unroll
    for (int j = 0; j < 8; ++j) {
        float4 v = rowp[lane + (j << 5)];
        x[j * 4 + 0] = v.x; x[j * 4 + 1] = v.y;
        x[j * 4 + 2] = v.z; x[j * 4 + 3] = v.w;
        m = fmaxf(m, fmaxf(fmaxf(v.x, v.y), fmaxf(v.z, v.w)));
    }
    #pragma unroll
    for (int o = 16; o; o >>= 1) m = fmaxf(m, __shfl_xor_sync(0xffffffffu, m, o));

    #pragma unroll
    for (int e = 0; e < 32; ++e) x[e] = (x[e] - m) * 0.5f;

    float tau = -1.0f;
    for (int it = 0; it < 16; ++it) {
        float s1 = 0.0f, s2 = 0.0f;
        #pragma unroll
        for (int e = 0; e < 32; ++e) {
            float t = fmaxf(x[e] - tau, 0.0f);
            s1 += t;
            s2 = fmaf(t, t, s2);
        }
        #pragma unroll
        for (int o = 16; o; o >>= 1) {
            s1 += __shfl_xor_sync(0xffffffffu, s1, o);
            s2 += __shfl_xor_sync(0xffffffffu, s2, o);
        }
        tau += (s2 - 1.0f) / (2.0f * s1);
        tau  = fminf(tau, -0.03125f);
        if (fabsf(s2 - 1.0f) < 2e-6f) break;
    }

    // ---- compaction: p = (x - tau)^2 for x > tau, with original key index.
    // element e=j*4+q on this lane corresponds to key (j*128 + lane*4 + q).
    float* pv = g_pvals + row * (size_t)S_;
    int*   pi = g_pidx  + row * (size_t)S_;
    int base = 0;
    #pragma unroll
    for (int j = 0; j < 8; ++j)
        #pragma unroll
        for (int qd = 0; qd < 4; ++qd) {
            float t = x[j * 4 + qd] - tau;
            unsigned bm = __ballot_sync(0xffffffffu, t > 0.0f);
            if (t > 0.0f) {
                int pos = base + __popc(bm & ((1u << lane) - 1u));
                pv[pos] = t * t;
                pi[pos] = j * 128 + lane * 4 + qd;
            }
            base += __popc(bm);
        }
    if (lane == 0) g_count[row] = base;
}

// ---------------------------------------------------------------------------
// Kernel 3: sparse out = P V. One warp per query row; lane owns dims
// [lane*4, lane*4+4). Loops over the row's support entries (typically ~10-30
// of 1024), fp32 exact. V rows are L2-hot (shared across query rows).
// ---------------------------------------------------------------------------
__global__ void __launch_bounds__(256) pv_sparse_kernel(const float* __restrict__ v,
                                                        float* __restrict__ out) {
    const int lane = threadIdx.x & 31;
    const int wid  = threadIdx.x >> 5;
    const size_t row = (size_t)blockIdx.x * 8 + wid;
    const int bh = (int)(row >> 10);

    const float* vg = v + (size_t)bh * S_ * D_ + (lane << 2);
    const float* pv = g_pvals + row * (size_t)S_;
    const int*   pi = g_pidx  + row * (size_t)S_;
    const int    cnt = g_count[row];

    float4 acc = make_float4(0.f, 0.f, 0.f, 0.f);

    int j = 0;
    for (; j + 4 <= cnt; j += 4) {
        float p0 = pv[j], p1 = pv[j + 1], p2 = pv[j + 2], p3 = pv[j + 3];
        int   i0 = pi[j], i1 = pi[j + 1], i2 = pi[j + 2], i3 = pi[j + 3];
        float4 v0 = *(const float4*)(vg + (size_t)i0 * D_);
        float4 v1 = *(const float4*)(vg + (size_t)i1 * D_);
        float4 v2 = *(const float4*)(vg + (size_t)i2 * D_);
        float4 v3 = *(const float4*)(vg + (size_t)i3 * D_);
        acc.x = fmaf(p0, v0.x, acc.x); acc.y = fmaf(p0, v0.y, acc.y);
        acc.z = fmaf(p0, v0.z, acc.z); acc.w = fmaf(p0, v0.w, acc.w);
        acc.x = fmaf(p1, v1.x, acc.x); acc.y = fmaf(p1, v1.y, acc.y);
        acc.z = fmaf(p1, v1.z, acc.z); acc.w = fmaf(p1, v1.w, acc.w);
        acc.x = fmaf(p2, v2.x, acc.x); acc.y = fmaf(p2, v2.y, acc.y);
        acc.z = fmaf(p2, v2.z, acc.z); acc.w = fmaf(p2, v2.w, acc.w);
        acc.x = fmaf(p3, v3.x, acc.x); acc.y = fmaf(p3, v3.y, acc.y);
        acc.z = fmaf(p3, v3.z, acc.z); acc.w = fmaf(p3, v3.w, acc.w);
    }
    for (; j < cnt; ++j) {
        float p = pv[j];
        float4 vv = *(const float4*)(vg + (size_t)pi[j] * D_);
        acc.x = fmaf(p, vv.x, acc.x); acc.y = fmaf(p, vv.y, acc.y);
        acc.z = fmaf(p, vv.z, acc.z); acc.w = fmaf(p, vv.w, acc.w);
    }

    *(float4*)(out + row * D_ + (lane << 2)) = acc;
}

// ---------------------------------------------------------------------------
extern "C" void kernel_launch(void* const* d_in, const int* in_sizes, int n_in,
                              void* d_out, int out_size) {
    (void)in_sizes; (void)n_in; (void)out_size;
    const float* q    = (const float*)d_in[0];
    const float* k    = (const float*)d_in[1];
    const float* v    = (const float*)d_in[2];
    const int*   mask = (const int*)d_in[3];
    float*       out  = (float*)d_out;

    constexpr int QK_SMEM = 61440;
    cudaFuncSetAttribute(qk_kernel, cudaFuncAttributeMaxDynamicSharedMemorySize, QK_SMEM);

    qk_kernel<<<dim3(16, 8, BH_), 256, QK_SMEM>>>(q, k, mask);
    entmax_kernel<<<BH_ * S_ / 16, 512>>>();
    pv_sparse_kernel<<<BH_ * S_ / 8, 256>>>(v, out);
}